// round 7
// baseline (speedup 1.0000x reference)
#include <cuda_runtime.h>
#include <cstdint>

#define NN 256
#define HH 4
#define DD 32
#define SCALE 0.1767766952966369f  /* 1/sqrt(32) */
#define L2E   1.4426950408889634f
#define M0L2E (14.0f * 1.4426950408889634f)

// ---------------- device globals ----------------
__device__ __align__(16) float g_trib[HH * NN * NN];  // [h][j][k] premult by log2(e)
__device__ __align__(16) float g_M[HH * DD * DD];     // per-head scale*Wq^T Wk  [c][d]
__device__ __align__(16) float g_qb[HH * DD];
__device__ __align__(16) float g_u[HH * DD];
__device__ float g_c0[HH];

// ---------------- helpers ----------------
__device__ __forceinline__ float hif(float x) {
    return __uint_as_float(__float_as_uint(x) & 0xFFFFE000u);
}
__device__ __forceinline__ float lof(float x, float h) {
    return __uint_as_float(__float_as_uint(x - h) & 0xFFFFE000u);
}
__device__ __forceinline__ float rnaf(float x) {
    uint32_t r; asm("cvt.rna.tf32.f32 %0, %1;" : "=r"(r) : "f"(x));
    return __uint_as_float(r);
}
__device__ __forceinline__ float ex2(float x) {
    float r; asm("ex2.approx.ftz.f32 %0, %1;" : "=f"(r) : "f"(x)); return r;
}
__device__ __forceinline__ void mma8(float* d, const uint32_t* a, uint32_t b0, uint32_t b1) {
    asm volatile("mma.sync.aligned.m16n8k8.row.col.f32.tf32.tf32.f32 "
        "{%0,%1,%2,%3},{%4,%5,%6,%7},{%8,%9},{%0,%1,%2,%3};"
        : "+f"(d[0]), "+f"(d[1]), "+f"(d[2]), "+f"(d[3])
        : "r"(a[0]), "r"(a[1]), "r"(a[2]), "r"(a[3]), "r"(b0), "r"(b1));
}
#define U(x) __float_as_uint(x)

// ---------------------------------------------------------------------------
// prep + trib fused: blocks [0,256) do trib rows, blocks [256,260) do prep
// ---------------------------------------------------------------------------
__global__ void __launch_bounds__(256) prep_trib_kernel(
        const float* __restrict__ x,  const float* __restrict__ Wb,
        const float* __restrict__ bb, const float* __restrict__ Wq,
        const float* __restrict__ bq, const float* __restrict__ Wk,
        const float* __restrict__ bk) {
    int t = threadIdx.x;
    if (blockIdx.x < NN) {
        int jj = blockIdx.x, k = t;
        const float4* xr = reinterpret_cast<const float4*>(x + ((size_t)jj * NN + k) * DD);
        float4 xv[8];
#pragma unroll
        for (int q = 0; q < 8; q++) xv[q] = xr[q];
#pragma unroll
        for (int h = 0; h < HH; h++) {
            const float4* wr = reinterpret_cast<const float4*>(Wb + h * DD);
            float s = bb[h];
#pragma unroll
            for (int q = 0; q < 8; q++) {
                float4 ww = wr[q];
                s += xv[q].x * ww.x + xv[q].y * ww.y + xv[q].z * ww.z + xv[q].w * ww.w;
            }
            g_trib[(h * NN + jj) * NN + k] = s * L2E;
        }
    } else {
        int h = blockIdx.x - NN;
        int d = t & 31, y = t >> 5;
#pragma unroll
        for (int cc = 0; cc < 4; cc++) {
            int c = y * 4 + cc;
            float s = 0.f;
#pragma unroll
            for (int r = 0; r < DD; r++)
                s += Wq[(h * DD + r) * DD + c] * Wk[(h * DD + r) * DD + d];
            g_M[(h * DD + c) * DD + d] = s * SCALE;
        }
        if (y == 0) {
            float s2 = 0.f, s3 = 0.f;
#pragma unroll
            for (int r = 0; r < DD; r++) {
                s2 += bq[h * DD + r] * Wk[(h * DD + r) * DD + d];
                s3 += Wq[(h * DD + r) * DD + d] * bk[h * DD + r];
            }
            g_qb[h * DD + d] = s2 * SCALE;
            g_u[h * DD + d]  = s3 * SCALE;
            if (d == 0) {
                float s4 = 0.f;
#pragma unroll
                for (int r = 0; r < DD; r++) s4 += bq[h * DD + r] * bk[h * DD + r];
                g_c0[h] = s4 * SCALE;
            }
        }
    }
}

// ---------------------------------------------------------------------------
// Fused attention: CTA=(i,h), 256 threads / 8 warps, warp = 32 query rows.
// Dynamic smem: XB (hi/lo float4 pairs, key-major), XT (rna tf32, transposed
// [d][key], float stride 264), PST (Q~/P/O staging).
// ---------------------------------------------------------------------------
#define S4X 20                 /* XB row stride in float4 per key   */
#define XT2STRF 264            /* XT row stride in floats per d     */
#define PSTR 36                /* PST row stride in floats          */
#define XB_OFF  0
#define XT2_OFF 81920          /* 256*20*16 */
#define PST_OFF 122880         /* XT uses 32*264*4 = 33792 <= 40960 */
#define DYN_BYTES 159744       /* + 256*36*4 */

extern __shared__ char dynsm[];

__global__ void __launch_bounds__(256, 1) attn_kernel(
        const float* __restrict__ x, const float* __restrict__ mask,
        const float* __restrict__ Wv, const float* __restrict__ bv,
        float* __restrict__ out) {
    const int i = blockIdx.x, h = blockIdx.y;
    const int t = threadIdx.x;
    const int w = t >> 5, lane = t & 31, g = lane >> 2, tc = lane & 3;
    const int R = w * 32;

    float4* xb4 = reinterpret_cast<float4*>(dynsm + XB_OFF);
    float2* xt2 = reinterpret_cast<float2*>(dynsm + XT2_OFF);
    float*  pst = reinterpret_cast<float*>(dynsm + PST_OFF);

    __shared__ __align__(16) float4 MB4s[DD * S4X];       // M hi/lo pairs
    __shared__ __align__(8)  float Wvh[DD * PSTR], Wvl[DD * PSTR];
    __shared__ __align__(8)  float mbsm[NN];
    __shared__ float basej[NN];
    __shared__ __align__(8)  float qbs[DD], bvs[DD];

    // ================= prologue =================
    {
        const int j = t;
        float xv[DD];
        const float4* xg = reinterpret_cast<const float4*>(x + ((size_t)i * NN + j) * DD);
#pragma unroll
        for (int q = 0; q < 8; q++) {
            float4 v = xg[q];
            xv[4*q] = v.x; xv[4*q+1] = v.y; xv[4*q+2] = v.z; xv[4*q+3] = v.w;
        }
        // XB: hi/lo pairs, key-major
#pragma unroll
        for (int kt = 0; kt < 4; kt++)
#pragma unroll
            for (int c = 0; c < 4; c++) {
                int d0 = kt * 8 + c;
                float h0 = hif(xv[d0]),     l0 = lof(xv[d0], h0);
                float h1 = hif(xv[d0 + 4]), l1 = lof(xv[d0 + 4], h1);
                xb4[j * S4X + kt * 4 + c] = make_float4(h0, l0, h1, l1);
            }
        // XT: rna tf32, transposed [d][key]; float2 slot pairs (key, key+4).
        // For key j: group = j>>3, off = j&7; float index =
        //   (group*4 + (off&3))*2 + (off>>2)  -> bijective 0..255 per d row.
        {
            float* xt2f = reinterpret_cast<float*>(xt2);
            int fi = (((j >> 3) * 4 + (j & 3)) << 1) + ((j >> 2) & 1);
#pragma unroll
            for (int d = 0; d < DD; d++)
                xt2f[d * XT2STRF + fi] = rnaf(xv[d]);
        }
        // MB4: M hi/lo pairs [d][kt][tc]
#pragma unroll
        for (int q = 0; q < 2; q++) {
            int e = t + q * 256;
            int d = e >> 4, r = e & 15, kt = r >> 2, cc = r & 3;
            int k0 = kt * 8 + cc;
            float m0 = g_M[((size_t)h * DD + k0) * DD + d];
            float m1 = g_M[((size_t)h * DD + k0 + 4) * DD + d];
            float h0 = hif(m0), h1 = hif(m1);
            MB4s[d * S4X + kt * 4 + cc] = make_float4(h0, lof(m0, h0), h1, lof(m1, h1));
        }
        // Wv hi/lo
#pragma unroll
        for (int q = 0; q < 4; q++) {
            int e = t + q * 256;
            int r = e >> 5, c = e & 31;
            float wv = Wv[((size_t)h * DD + r) * DD + c];
            float hh = hif(wv);
            Wvh[r * PSTR + c] = hh;
            Wvl[r * PSTR + c] = lof(wv, hh);
        }
        if (t < DD) qbs[t] = g_qb[h * DD + t];
        else if (t < 2 * DD) bvs[t - DD] = bv[h * DD + (t - DD)];
        mbsm[j] = (mask[i * NN + j] - 1.0f) * 1e9f * L2E;
        float cbv = g_c0[h];
#pragma unroll
        for (int c = 0; c < DD; c++) cbv += xv[c] * g_u[h * DD + c];
        basej[j] = cbv * L2E - M0L2E;
    }
    __syncthreads();

    // ================= Q~ = X M + qb via 3xTF32 mma =================
    {
        float qt0[16], qt1[16];
#pragma unroll
        for (int q = 0; q < 16; q++) { qt0[q] = 0.f; qt1[q] = 0.f; }
#pragma unroll
        for (int kt = 0; kt < 4; kt++) {
            float4 fA0 = xb4[(R + g     ) * S4X + kt * 4 + tc];
            float4 fA1 = xb4[(R + g + 8 ) * S4X + kt * 4 + tc];
            float4 fB0 = xb4[(R + g + 16) * S4X + kt * 4 + tc];
            float4 fB1 = xb4[(R + g + 24) * S4X + kt * 4 + tc];
            uint32_t ah0[4] = {U(fA0.x), U(fA1.x), U(fA0.z), U(fA1.z)};
            uint32_t al0[4] = {U(fA0.y), U(fA1.y), U(fA0.w), U(fA1.w)};
            uint32_t ah1[4] = {U(fB0.x), U(fB1.x), U(fB0.z), U(fB1.z)};
            uint32_t al1[4] = {U(fB0.y), U(fB1.y), U(fB0.w), U(fB1.w)};
#pragma unroll
            for (int nt = 0; nt < 4; nt++) {
                float4 bm = MB4s[(nt * 8 + g) * S4X + kt * 4 + tc];
                mma8(&qt0[nt*4], ah0, U(bm.x), U(bm.z));
                mma8(&qt0[nt*4], ah0, U(bm.y), U(bm.w));
                mma8(&qt0[nt*4], al0, U(bm.x), U(bm.z));
                mma8(&qt1[nt*4], ah1, U(bm.x), U(bm.z));
                mma8(&qt1[nt*4], ah1, U(bm.y), U(bm.w));
                mma8(&qt1[nt*4], al1, U(bm.x), U(bm.z));
            }
        }
#pragma unroll
        for (int nt = 0; nt < 4; nt++) {
            int c0 = nt * 8 + 2 * tc;
            float2 qb2 = *reinterpret_cast<const float2*>(&qbs[c0]);
            *reinterpret_cast<float2*>(&pst[(R + g     ) * PSTR + c0]) = make_float2(qt0[nt*4+0] + qb2.x, qt0[nt*4+1] + qb2.y);
            *reinterpret_cast<float2*>(&pst[(R + g + 8 ) * PSTR + c0]) = make_float2(qt0[nt*4+2] + qb2.x, qt0[nt*4+3] + qb2.y);
            *reinterpret_cast<float2*>(&pst[(R + g + 16) * PSTR + c0]) = make_float2(qt1[nt*4+0] + qb2.x, qt1[nt*4+1] + qb2.y);
            *reinterpret_cast<float2*>(&pst[(R + g + 24) * PSTR + c0]) = make_float2(qt1[nt*4+2] + qb2.x, qt1[nt*4+3] + qb2.y);
        }
    }
    __syncwarp();

    // Q fragments (hi/lo split), persistent
    uint32_t qh0[16], ql0[16], qh1[16], ql1[16];
#pragma unroll
    for (int kt = 0; kt < 4; kt++) {
        float q00 = pst[(R + g     ) * PSTR + kt*8 + tc];
        float q01 = pst[(R + g + 8 ) * PSTR + kt*8 + tc];
        float q02 = pst[(R + g     ) * PSTR + kt*8 + tc + 4];
        float q03 = pst[(R + g + 8 ) * PSTR + kt*8 + tc + 4];
        float q10 = pst[(R + g + 16) * PSTR + kt*8 + tc];
        float q11 = pst[(R + g + 24) * PSTR + kt*8 + tc];
        float q12 = pst[(R + g + 16) * PSTR + kt*8 + tc + 4];
        float q13 = pst[(R + g + 24) * PSTR + kt*8 + tc + 4];
        qh0[kt*4+0] = U(hif(q00)); ql0[kt*4+0] = U(lof(q00, hif(q00)));
        qh0[kt*4+1] = U(hif(q01)); ql0[kt*4+1] = U(lof(q01, hif(q01)));
        qh0[kt*4+2] = U(hif(q02)); ql0[kt*4+2] = U(lof(q02, hif(q02)));
        qh0[kt*4+3] = U(hif(q03)); ql0[kt*4+3] = U(lof(q03, hif(q03)));
        qh1[kt*4+0] = U(hif(q10)); ql1[kt*4+0] = U(lof(q10, hif(q10)));
        qh1[kt*4+1] = U(hif(q11)); ql1[kt*4+1] = U(lof(q11, hif(q11)));
        qh1[kt*4+2] = U(hif(q12)); ql1[kt*4+2] = U(lof(q12, hif(q12)));
        qh1[kt*4+3] = U(hif(q13)); ql1[kt*4+3] = U(lof(q13, hif(q13)));
    }
    const float base0 = basej[R + g], base1 = basej[R + g + 8];
    const float base2 = basej[R + g + 16], base3 = basej[R + g + 24];

    float o0[16], o1[16];
#pragma unroll
    for (int q = 0; q < 16; q++) { o0[q] = 0.f; o1[q] = 0.f; }
    float l0 = 0.f, l1 = 0.f, l2 = 0.f, l3 = 0.f;

    const float* tp0 = g_trib + ((size_t)(h * NN + R + g)) * NN;
    __syncwarp();

    // ================= main loop: 8 key-blocks of 32 =================
#pragma unroll 1
    for (int kb = 0; kb < NN; kb += 32) {
        // trib prefetch (L2 resident)
        float2 tb[16];
#pragma unroll
        for (int m = 0; m < 4; m++)
#pragma unroll
            for (int nt = 0; nt < 4; nt++)
                tb[m*4+nt] = *reinterpret_cast<const float2*>(tp0 + (size_t)m * 8 * NN + kb + nt*8 + 2*tc);

        // ---- MMA1: S = Q~ X^T (3xTF32), B shared across both m-tiles ----
        float s0[16], s1[16];
#pragma unroll
        for (int q = 0; q < 16; q++) { s0[q] = 0.f; s1[q] = 0.f; }
#pragma unroll
        for (int kt = 0; kt < 4; kt++) {
#pragma unroll
            for (int nt = 0; nt < 4; nt++) {
                float4 xb = xb4[(kb + nt*8 + g) * S4X + kt * 4 + tc];
                uint32_t bh0 = U(xb.x), bl0 = U(xb.y), bh1 = U(xb.z), bl1 = U(xb.w);
                mma8(&s0[nt*4], &qh0[kt*4], bh0, bh1);
                mma8(&s0[nt*4], &qh0[kt*4], bl0, bl1);
                mma8(&s0[nt*4], &ql0[kt*4], bh0, bh1);
                mma8(&s1[nt*4], &qh1[kt*4], bh0, bh1);
                mma8(&s1[nt*4], &qh1[kt*4], bl0, bl1);
                mma8(&s1[nt*4], &ql1[kt*4], bh0, bh1);
            }
        }

        // ---- softmax on fragments; P (tf32-rounded) -> stage ----
#pragma unroll
        for (int nt = 0; nt < 4; nt++) {
            float2 mv = *reinterpret_cast<const float2*>(&mbsm[kb + nt*8 + 2*tc]);
            float t00 = rnaf(ex2(fmaf(s0[nt*4+0], L2E, base0 + mv.x + tb[nt].x)));
            float t01 = rnaf(ex2(fmaf(s0[nt*4+1], L2E, base0 + mv.y + tb[nt].y)));
            float t02 = rnaf(ex2(fmaf(s0[nt*4+2], L2E, base1 + mv.x + tb[4+nt].x)));
            float t03 = rnaf(ex2(fmaf(s0[nt*4+3], L2E, base1 + mv.y + tb[4+nt].y)));
            float t10 = rnaf(ex2(fmaf(s1[nt*4+0], L2E, base2 + mv.x + tb[8+nt].x)));
            float t11 = rnaf(ex2(fmaf(s1[nt*4+1], L2E, base2 + mv.y + tb[8+nt].y)));
            float t12 = rnaf(ex2(fmaf(s1[nt*4+2], L2E, base3 + mv.x + tb[12+nt].x)));
            float t13 = rnaf(ex2(fmaf(s1[nt*4+3], L2E, base3 + mv.y + tb[12+nt].y)));
            l0 += t00 + t01; l1 += t02 + t03; l2 += t10 + t11; l3 += t12 + t13;
            int c0 = nt * 8 + 2 * tc;
            *reinterpret_cast<float2*>(&pst[(R + g     ) * PSTR + c0]) = make_float2(t00, t01);
            *reinterpret_cast<float2*>(&pst[(R + g + 8 ) * PSTR + c0]) = make_float2(t02, t03);
            *reinterpret_cast<float2*>(&pst[(R + g + 16) * PSTR + c0]) = make_float2(t10, t11);
            *reinterpret_cast<float2*>(&pst[(R + g + 24) * PSTR + c0]) = make_float2(t12, t13);
        }
        __syncwarp();

        // ---- MMA2: O += P X (single-pass tf32, rna-rounded X) ----
#pragma unroll
        for (int kt = 0; kt < 4; kt++) {
            uint32_t a0[4], a1[4];
            a0[0] = U(pst[(R + g     ) * PSTR + kt*8 + tc]);
            a0[1] = U(pst[(R + g + 8 ) * PSTR + kt*8 + tc]);
            a0[2] = U(pst[(R + g     ) * PSTR + kt*8 + tc + 4]);
            a0[3] = U(pst[(R + g + 8 ) * PSTR + kt*8 + tc + 4]);
            a1[0] = U(pst[(R + g + 16) * PSTR + kt*8 + tc]);
            a1[1] = U(pst[(R + g + 24) * PSTR + kt*8 + tc]);
            a1[2] = U(pst[(R + g + 16) * PSTR + kt*8 + tc + 4]);
            a1[3] = U(pst[(R + g + 24) * PSTR + kt*8 + tc + 4]);
#pragma unroll
            for (int nt = 0; nt < 4; nt++) {
                // B[n=d][k=key]: key = kb + kt*8 + tc (pair with key+4)
                float2 xt = xt2[(nt*8 + g) * (XT2STRF / 2) + ((kb >> 3) + kt) * 4 + tc];
                mma8(&o0[nt*4], a0, U(xt.x), U(xt.y));
                mma8(&o1[nt*4], a1, U(xt.x), U(xt.y));
            }
        }
        __syncwarp();
    }

    // ================= epilogue: F = (O Wv^T)/l + bv (3xTF32) =================
#pragma unroll
    for (int nt = 0; nt < 4; nt++) {
        int c0 = nt * 8 + 2 * tc;
        *reinterpret_cast<float2*>(&pst[(R + g     ) * PSTR + c0]) = make_float2(o0[nt*4+0], o0[nt*4+1]);
        *reinterpret_cast<float2*>(&pst[(R + g + 8 ) * PSTR + c0]) = make_float2(o0[nt*4+2], o0[nt*4+3]);
        *reinterpret_cast<float2*>(&pst[(R + g + 16) * PSTR + c0]) = make_float2(o1[nt*4+0], o1[nt*4+1]);
        *reinterpret_cast<float2*>(&pst[(R + g + 24) * PSTR + c0]) = make_float2(o1[nt*4+2], o1[nt*4+3]);
    }
    __syncwarp();

    float f0[16], f1[16];
#pragma unroll
    for (int q = 0; q < 16; q++) { f0[q] = 0.f; f1[q] = 0.f; }
#pragma unroll
    for (int kt = 0; kt < 4; kt++) {
        float v00 = pst[(R + g     ) * PSTR + kt*8 + tc];
        float v01 = pst[(R + g + 8 ) * PSTR + kt*8 + tc];
        float v02 = pst[(R + g     ) * PSTR + kt*8 + tc + 4];
        float v03 = pst[(R + g + 8 ) * PSTR + kt*8 + tc + 4];
        float v10 = pst[(R + g + 16) * PSTR + kt*8 + tc];
        float v11 = pst[(R + g + 24) * PSTR + kt*8 + tc];
        float v12 = pst[(R + g + 16) * PSTR + kt*8 + tc + 4];
        float v13 = pst[(R + g + 24) * PSTR + kt*8 + tc + 4];
        uint32_t oh0[4] = {U(hif(v00)), U(hif(v01)), U(hif(v02)), U(hif(v03))};
        uint32_t ol0[4] = {U(lof(v00, hif(v00))), U(lof(v01, hif(v01))), U(lof(v02, hif(v02))), U(lof(v03, hif(v03)))};
        uint32_t oh1[4] = {U(hif(v10)), U(hif(v11)), U(hif(v12)), U(hif(v13))};
        uint32_t ol1[4] = {U(lof(v10, hif(v10))), U(lof(v11, hif(v11))), U(lof(v12, hif(v12))), U(lof(v13, hif(v13)))};
#pragma unroll
        for (int nt = 0; nt < 4; nt++) {
            uint32_t bh0 = U(Wvh[(nt*8 + g) * PSTR + kt*8 + tc]);
            uint32_t bh1 = U(Wvh[(nt*8 + g) * PSTR + kt*8 + tc + 4]);
            uint32_t bl0 = U(Wvl[(nt*8 + g) * PSTR + kt*8 + tc]);
            uint32_t bl1 = U(Wvl[(nt*8 + g) * PSTR + kt*8 + tc + 4]);
            mma8(&f0[nt*4], oh0, bh0, bh1);
            mma8(&f0[nt*4], oh0, bl0, bl1);
            mma8(&f0[nt*4], ol0, bh0, bh1);
            mma8(&f1[nt*4], oh1, bh0, bh1);
            mma8(&f1[nt*4], oh1, bl0, bl1);
            mma8(&f1[nt*4], ol1, bh0, bh1);
        }
    }

    l0 += __shfl_xor_sync(0xFFFFFFFFu, l0, 1); l0 += __shfl_xor_sync(0xFFFFFFFFu, l0, 2);
    l1 += __shfl_xor_sync(0xFFFFFFFFu, l1, 1); l1 += __shfl_xor_sync(0xFFFFFFFFu, l1, 2);
    l2 += __shfl_xor_sync(0xFFFFFFFFu, l2, 1); l2 += __shfl_xor_sync(0xFFFFFFFFu, l2, 2);
    l3 += __shfl_xor_sync(0xFFFFFFFFu, l3, 1); l3 += __shfl_xor_sync(0xFFFFFFFFu, l3, 2);
    float inv0 = 1.f / l0, inv1 = 1.f / l1, inv2 = 1.f / l2, inv3 = 1.f / l3;

#pragma unroll
    for (int nt = 0; nt < 4; nt++) {
        int c0 = nt * 8 + 2 * tc;
        float2 bb2 = *reinterpret_cast<const float2*>(&bvs[c0]);
        float2 v0 = make_float2(f0[nt*4+0] * inv0 + bb2.x, f0[nt*4+1] * inv0 + bb2.y);
        float2 v1 = make_float2(f0[nt*4+2] * inv1 + bb2.x, f0[nt*4+3] * inv1 + bb2.y);
        float2 v2 = make_float2(f1[nt*4+0] * inv2 + bb2.x, f1[nt*4+1] * inv2 + bb2.y);
        float2 v3 = make_float2(f1[nt*4+2] * inv3 + bb2.x, f1[nt*4+3] * inv3 + bb2.y);
        *reinterpret_cast<float2*>(out + (((size_t)i * NN + R + g     ) * HH + h) * DD + c0) = v0;
        *reinterpret_cast<float2*>(out + (((size_t)i * NN + R + g + 8 ) * HH + h) * DD + c0) = v1;
        *reinterpret_cast<float2*>(out + (((size_t)i * NN + R + g + 16) * HH + h) * DD + c0) = v2;
        *reinterpret_cast<float2*>(out + (((size_t)i * NN + R + g + 24) * HH + h) * DD + c0) = v3;
    }
}

// ---------------------------------------------------------------------------
extern "C" void kernel_launch(void* const* d_in, const int* in_sizes, int n_in,
                              void* d_out, int out_size) {
    const float* x    = (const float*)d_in[0];
    const float* mask = (const float*)d_in[1];
    const float* Wq   = (const float*)d_in[2];
    const float* bq   = (const float*)d_in[3];
    const float* Wk   = (const float*)d_in[4];
    const float* bk   = (const float*)d_in[5];
    const float* Wv   = (const float*)d_in[6];
    const float* bv   = (const float*)d_in[7];
    const float* Wb   = (const float*)d_in[8];
    const float* bb   = (const float*)d_in[9];
    float* out = (float*)d_out;

    cudaFuncSetAttribute(attn_kernel, cudaFuncAttributeMaxDynamicSharedMemorySize, DYN_BYTES);

    prep_trib_kernel<<<NN + HH, 256>>>(x, Wb, bb, Wq, bq, Wk, bk);
    attn_kernel<<<dim3(NN, HH), 256, DYN_BYTES>>>(x, mask, Wv, bv, out);
}

// round 8
// speedup vs baseline: 1.1930x; 1.1930x over previous
#include <cuda_runtime.h>
#include <cstdint>

#define NN 256
#define HH 4
#define DD 32
#define SCALE 0.1767766952966369f  /* 1/sqrt(32) */
#define L2E   1.4426950408889634f
#define M0L2E (14.0f * 1.4426950408889634f)

// ---------------- device globals ----------------
__device__ __align__(16) float g_trib[HH * NN * NN];  // [h][j][k] premult by log2(e)
__device__ __align__(16) float g_M[HH * DD * DD];     // per-head scale*Wq^T Wk  [c][d]
__device__ __align__(16) float g_qb[HH * DD];
__device__ __align__(16) float g_u[HH * DD];
__device__ float g_c0[HH];

// ---------------- helpers ----------------
__device__ __forceinline__ float hif(float x) {
    return __uint_as_float(__float_as_uint(x) & 0xFFFFE000u);
}
__device__ __forceinline__ float lof(float x, float h) {
    return __uint_as_float(__float_as_uint(x - h) & 0xFFFFE000u);
}
__device__ __forceinline__ float rnaf(float x) {
    uint32_t r; asm("cvt.rna.tf32.f32 %0, %1;" : "=r"(r) : "f"(x));
    return __uint_as_float(r);
}
__device__ __forceinline__ float ex2(float x) {
    float r; asm("ex2.approx.ftz.f32 %0, %1;" : "=f"(r) : "f"(x)); return r;
}
__device__ __forceinline__ void mma8(float* d, const uint32_t* a, uint32_t b0, uint32_t b1) {
    asm volatile("mma.sync.aligned.m16n8k8.row.col.f32.tf32.tf32.f32 "
        "{%0,%1,%2,%3},{%4,%5,%6,%7},{%8,%9},{%0,%1,%2,%3};"
        : "+f"(d[0]), "+f"(d[1]), "+f"(d[2]), "+f"(d[3])
        : "r"(a[0]), "r"(a[1]), "r"(a[2]), "r"(a[3]), "r"(b0), "r"(b1));
}
#define U(x) __float_as_uint(x)

// ---------------------------------------------------------------------------
// prep + trib fused
// ---------------------------------------------------------------------------
__global__ void __launch_bounds__(256) prep_trib_kernel(
        const float* __restrict__ x,  const float* __restrict__ Wb,
        const float* __restrict__ bb, const float* __restrict__ Wq,
        const float* __restrict__ bq, const float* __restrict__ Wk,
        const float* __restrict__ bk) {
    int t = threadIdx.x;
    if (blockIdx.x < NN) {
        int jj = blockIdx.x, k = t;
        const float4* xr = reinterpret_cast<const float4*>(x + ((size_t)jj * NN + k) * DD);
        float4 xv[8];
#pragma unroll
        for (int q = 0; q < 8; q++) xv[q] = xr[q];
#pragma unroll
        for (int h = 0; h < HH; h++) {
            const float4* wr = reinterpret_cast<const float4*>(Wb + h * DD);
            float s = bb[h];
#pragma unroll
            for (int q = 0; q < 8; q++) {
                float4 ww = wr[q];
                s += xv[q].x * ww.x + xv[q].y * ww.y + xv[q].z * ww.z + xv[q].w * ww.w;
            }
            g_trib[(h * NN + jj) * NN + k] = s * L2E;
        }
    } else {
        int h = blockIdx.x - NN;
        int d = t & 31, y = t >> 5;
#pragma unroll
        for (int cc = 0; cc < 4; cc++) {
            int c = y * 4 + cc;
            float s = 0.f;
#pragma unroll
            for (int r = 0; r < DD; r++)
                s += Wq[(h * DD + r) * DD + c] * Wk[(h * DD + r) * DD + d];
            g_M[(h * DD + c) * DD + d] = s * SCALE;
        }
        if (y == 0) {
            float s2 = 0.f, s3 = 0.f;
#pragma unroll
            for (int r = 0; r < DD; r++) {
                s2 += bq[h * DD + r] * Wk[(h * DD + r) * DD + d];
                s3 += Wq[(h * DD + r) * DD + d] * bk[h * DD + r];
            }
            g_qb[h * DD + d] = s2 * SCALE;
            g_u[h * DD + d]  = s3 * SCALE;
            if (d == 0) {
                float s4 = 0.f;
#pragma unroll
                for (int r = 0; r < DD; r++) s4 += bq[h * DD + r] * bk[h * DD + r];
                g_c0[h] = s4 * SCALE;
            }
        }
    }
}

// ---------------------------------------------------------------------------
// Fused attention: CTA=(i,h), 256 threads / 8 warps, warp = 32 query rows.
// Smem: XB  = rna(X) (d,d+4) float2 pairs, key-major, stride 20 float2
//       XT  = rna(X) transposed [d][key-pairs], stride 264 floats
//       PST = staging (Q~/P/O), stride 36 floats, XOR-swizzled columns
// ---------------------------------------------------------------------------
#define XB_OFF  0
#define XT_OFF  40960          /* 256*40*4 */
#define PST_OFF 74752          /* + 32*264*4 */
#define DYN_BYTES 111616       /* + 256*36*4 */
#define XTSTR 264

// PST index with bank-conflict-free XOR swizzle (reads & writes both bijective)
__device__ __forceinline__ int psti(int row, int col) {
    return row * 36 + (col ^ ((row & 3) << 3));
}

extern __shared__ char dynsm[];

__global__ void __launch_bounds__(256, 1) attn_kernel(
        const float* __restrict__ x, const float* __restrict__ mask,
        const float* __restrict__ Wv, const float* __restrict__ bv,
        float* __restrict__ out) {
    const int i = blockIdx.x, h = blockIdx.y;
    const int t = threadIdx.x;
    const int w = t >> 5, lane = t & 31, g = lane >> 2, tc = lane & 3;
    const int R = w * 32;

    float2* xb2 = reinterpret_cast<float2*>(dynsm + XB_OFF);
    float*  xtf = reinterpret_cast<float*>(dynsm + XT_OFF);
    float*  pst = reinterpret_cast<float*>(dynsm + PST_OFF);

    __shared__ __align__(16) float4 MB4s[DD * 20];        // M hi/lo pairs
    __shared__ __align__(8)  float Wvh[DD * 36], Wvl[DD * 36];
    __shared__ __align__(8)  float mbsm[NN];
    __shared__ float basej[NN];
    __shared__ __align__(8)  float qbs[DD], bvs[DD];

    // ================= prologue =================
    {
        const int j = t;
        float xv[DD], xr[DD];
        const float4* xg = reinterpret_cast<const float4*>(x + ((size_t)i * NN + j) * DD);
#pragma unroll
        for (int q = 0; q < 8; q++) {
            float4 v = xg[q];
            xv[4*q] = v.x; xv[4*q+1] = v.y; xv[4*q+2] = v.z; xv[4*q+3] = v.w;
        }
#pragma unroll
        for (int d = 0; d < DD; d++) xr[d] = rnaf(xv[d]);

        // XB: (d, d+4) pairs, key-major; float4 covers pairs (d,d+1)
        {
            float4* xb4 = reinterpret_cast<float4*>(dynsm + XB_OFF);
#pragma unroll
            for (int kt = 0; kt < 4; kt++)
#pragma unroll
                for (int c = 0; c < 2; c++) {
                    int d0 = kt * 8 + 2 * c;
                    xb4[j * 10 + kt * 2 + c] =
                        make_float4(xr[d0], xr[d0 + 4], xr[d0 + 1], xr[d0 + 5]);
                }
        }
        // XT: transposed [d][key]; float slot fi pairs (key, key+4)
        {
            int fi = (((j >> 3) * 4 + (j & 3)) << 1) + ((j >> 2) & 1);
#pragma unroll
            for (int d = 0; d < DD; d++)
                xtf[d * XTSTR + fi] = xr[d];
        }
        // MB4s: M hi/lo pairs [d][kt][tc]
#pragma unroll
        for (int q = 0; q < 2; q++) {
            int e = t + q * 256;
            int d = e >> 4, r = e & 15, kt = r >> 2, cc = r & 3;
            int k0 = kt * 8 + cc;
            float m0 = g_M[((size_t)h * DD + k0) * DD + d];
            float m1 = g_M[((size_t)h * DD + k0 + 4) * DD + d];
            float h0 = hif(m0), h1 = hif(m1);
            MB4s[d * 20 + kt * 4 + cc] = make_float4(h0, lof(m0, h0), h1, lof(m1, h1));
        }
        // Wv hi/lo
#pragma unroll
        for (int q = 0; q < 4; q++) {
            int e = t + q * 256;
            int r = e >> 5, c = e & 31;
            float wv = Wv[((size_t)h * DD + r) * DD + c];
            float hh = hif(wv);
            Wvh[r * 36 + c] = hh;
            Wvl[r * 36 + c] = lof(wv, hh);
        }
        if (t < DD) qbs[t] = g_qb[h * DD + t];
        else if (t < 2 * DD) bvs[t - DD] = bv[h * DD + (t - DD)];
        mbsm[j] = (mask[i * NN + j] - 1.0f) * 1e9f * L2E;
        float cbv = g_c0[h];
#pragma unroll
        for (int c = 0; c < DD; c++) cbv += xv[c] * g_u[h * DD + c];
        basej[j] = cbv * L2E - M0L2E;
    }
    __syncthreads();

    // ================= Q~ = X M + qb (A = rna(X), B = Mh/Ml 2-pass) =========
    {
        float qt0[16], qt1[16];
#pragma unroll
        for (int q = 0; q < 16; q++) { qt0[q] = 0.f; qt1[q] = 0.f; }
#pragma unroll
        for (int kt = 0; kt < 4; kt++) {
            float2 pA0 = xb2[(R + g     ) * 20 + kt * 4 + tc];
            float2 pA1 = xb2[(R + g + 8 ) * 20 + kt * 4 + tc];
            float2 pB0 = xb2[(R + g + 16) * 20 + kt * 4 + tc];
            float2 pB1 = xb2[(R + g + 24) * 20 + kt * 4 + tc];
            uint32_t a0[4] = {U(pA0.x), U(pA1.x), U(pA0.y), U(pA1.y)};
            uint32_t a1[4] = {U(pB0.x), U(pB1.x), U(pB0.y), U(pB1.y)};
#pragma unroll
            for (int nt = 0; nt < 4; nt++) {
                float4 bm = MB4s[(nt * 8 + g) * 20 + kt * 4 + tc];
                mma8(&qt0[nt*4], a0, U(bm.x), U(bm.z));
                mma8(&qt0[nt*4], a0, U(bm.y), U(bm.w));
                mma8(&qt1[nt*4], a1, U(bm.x), U(bm.z));
                mma8(&qt1[nt*4], a1, U(bm.y), U(bm.w));
            }
        }
#pragma unroll
        for (int nt = 0; nt < 4; nt++) {
            int c0 = nt * 8 + 2 * tc;
            float2 qb2 = *reinterpret_cast<const float2*>(&qbs[c0]);
            *reinterpret_cast<float2*>(&pst[psti(R + g     , c0)]) =
                make_float2(rnaf(qt0[nt*4+0] + qb2.x), rnaf(qt0[nt*4+1] + qb2.y));
            *reinterpret_cast<float2*>(&pst[psti(R + g + 8 , c0)]) =
                make_float2(rnaf(qt0[nt*4+2] + qb2.x), rnaf(qt0[nt*4+3] + qb2.y));
            *reinterpret_cast<float2*>(&pst[psti(R + g + 16, c0)]) =
                make_float2(rnaf(qt1[nt*4+0] + qb2.x), rnaf(qt1[nt*4+1] + qb2.y));
            *reinterpret_cast<float2*>(&pst[psti(R + g + 24, c0)]) =
                make_float2(rnaf(qt1[nt*4+2] + qb2.x), rnaf(qt1[nt*4+3] + qb2.y));
        }
    }
    __syncwarp();

    // Persistent Q fragments (rna tf32, single array per m-tile)
    uint32_t q0[16], q1[16];
#pragma unroll
    for (int kt = 0; kt < 4; kt++) {
        q0[kt*4+0] = U(pst[psti(R + g     , kt*8 + tc)]);
        q0[kt*4+1] = U(pst[psti(R + g + 8 , kt*8 + tc)]);
        q0[kt*4+2] = U(pst[psti(R + g     , kt*8 + tc + 4)]);
        q0[kt*4+3] = U(pst[psti(R + g + 8 , kt*8 + tc + 4)]);
        q1[kt*4+0] = U(pst[psti(R + g + 16, kt*8 + tc)]);
        q1[kt*4+1] = U(pst[psti(R + g + 24, kt*8 + tc)]);
        q1[kt*4+2] = U(pst[psti(R + g + 16, kt*8 + tc + 4)]);
        q1[kt*4+3] = U(pst[psti(R + g + 24, kt*8 + tc + 4)]);
    }
    const float base0 = basej[R + g], base1 = basej[R + g + 8];
    const float base2 = basej[R + g + 16], base3 = basej[R + g + 24];

    float o0[16], o1[16];
#pragma unroll
    for (int q = 0; q < 16; q++) { o0[q] = 0.f; o1[q] = 0.f; }
    float l0 = 0.f, l1 = 0.f, l2 = 0.f, l3 = 0.f;

    const float* tp0 = g_trib + ((size_t)(h * NN + R + g)) * NN;
    __syncwarp();

    // ================= main loop: 8 key-blocks of 32 =================
#pragma unroll 1
    for (int kb = 0; kb < NN; kb += 32) {
        // trib prefetch (L2 resident)
        float2 tb[16];
#pragma unroll
        for (int m = 0; m < 4; m++)
#pragma unroll
            for (int nt = 0; nt < 4; nt++)
                tb[m*4+nt] = *reinterpret_cast<const float2*>(tp0 + (size_t)m * 8 * NN + kb + nt*8 + 2*tc);

        // ---- MMA1: S = Q~ X^T (single tf32 pass, rna operands) ----
        float s0[16], s1[16];
#pragma unroll
        for (int q = 0; q < 16; q++) { s0[q] = 0.f; s1[q] = 0.f; }
#pragma unroll
        for (int kt = 0; kt < 4; kt++) {
#pragma unroll
            for (int nt = 0; nt < 4; nt++) {
                float2 xb = xb2[(kb + nt*8 + g) * 20 + kt * 4 + tc];
                mma8(&s0[nt*4], &q0[kt*4], U(xb.x), U(xb.y));
                mma8(&s1[nt*4], &q1[kt*4], U(xb.x), U(xb.y));
            }
        }

        // ---- softmax on fragments; P (rna tf32) -> swizzled stage ----
#pragma unroll
        for (int nt = 0; nt < 4; nt++) {
            float2 mv = *reinterpret_cast<const float2*>(&mbsm[kb + nt*8 + 2*tc]);
            float t00 = rnaf(ex2(fmaf(s0[nt*4+0], L2E, base0 + mv.x + tb[nt].x)));
            float t01 = rnaf(ex2(fmaf(s0[nt*4+1], L2E, base0 + mv.y + tb[nt].y)));
            float t02 = rnaf(ex2(fmaf(s0[nt*4+2], L2E, base1 + mv.x + tb[4+nt].x)));
            float t03 = rnaf(ex2(fmaf(s0[nt*4+3], L2E, base1 + mv.y + tb[4+nt].y)));
            float t10 = rnaf(ex2(fmaf(s1[nt*4+0], L2E, base2 + mv.x + tb[8+nt].x)));
            float t11 = rnaf(ex2(fmaf(s1[nt*4+1], L2E, base2 + mv.y + tb[8+nt].y)));
            float t12 = rnaf(ex2(fmaf(s1[nt*4+2], L2E, base3 + mv.x + tb[12+nt].x)));
            float t13 = rnaf(ex2(fmaf(s1[nt*4+3], L2E, base3 + mv.y + tb[12+nt].y)));
            l0 += t00 + t01; l1 += t02 + t03; l2 += t10 + t11; l3 += t12 + t13;
            int c0 = nt * 8 + 2 * tc;
            *reinterpret_cast<float2*>(&pst[psti(R + g     , c0)]) = make_float2(t00, t01);
            *reinterpret_cast<float2*>(&pst[psti(R + g + 8 , c0)]) = make_float2(t02, t03);
            *reinterpret_cast<float2*>(&pst[psti(R + g + 16, c0)]) = make_float2(t10, t11);
            *reinterpret_cast<float2*>(&pst[psti(R + g + 24, c0)]) = make_float2(t12, t13);
        }
        __syncwarp();

        // ---- MMA2: O += P X (single-pass tf32) ----
#pragma unroll
        for (int kt = 0; kt < 4; kt++) {
            uint32_t a0[4], a1[4];
            a0[0] = U(pst[psti(R + g     , kt*8 + tc)]);
            a0[1] = U(pst[psti(R + g + 8 , kt*8 + tc)]);
            a0[2] = U(pst[psti(R + g     , kt*8 + tc + 4)]);
            a0[3] = U(pst[psti(R + g + 8 , kt*8 + tc + 4)]);
            a1[0] = U(pst[psti(R + g + 16, kt*8 + tc)]);
            a1[1] = U(pst[psti(R + g + 24, kt*8 + tc)]);
            a1[2] = U(pst[psti(R + g + 16, kt*8 + tc + 4)]);
            a1[3] = U(pst[psti(R + g + 24, kt*8 + tc + 4)]);
#pragma unroll
            for (int nt = 0; nt < 4; nt++) {
                float2 xt = *reinterpret_cast<const float2*>(
                    &xtf[(nt*8 + g) * XTSTR + (((kb >> 3) + kt) * 4 + tc) * 2]);
                mma8(&o0[nt*4], a0, U(xt.x), U(xt.y));
                mma8(&o1[nt*4], a1, U(xt.x), U(xt.y));
            }
        }
        __syncwarp();
    }

    // ================= epilogue: F = (O Wv^T)/l + bv (3xTF32) =================
#pragma unroll
    for (int nt = 0; nt < 4; nt++) {
        int c0 = nt * 8 + 2 * tc;
        *reinterpret_cast<float2*>(&pst[psti(R + g     , c0)]) = make_float2(o0[nt*4+0], o0[nt*4+1]);
        *reinterpret_cast<float2*>(&pst[psti(R + g + 8 , c0)]) = make_float2(o0[nt*4+2], o0[nt*4+3]);
        *reinterpret_cast<float2*>(&pst[psti(R + g + 16, c0)]) = make_float2(o1[nt*4+0], o1[nt*4+1]);
        *reinterpret_cast<float2*>(&pst[psti(R + g + 24, c0)]) = make_float2(o1[nt*4+2], o1[nt*4+3]);
    }
    __syncwarp();

    float f0[16], f1[16];
#pragma unroll
    for (int q = 0; q < 16; q++) { f0[q] = 0.f; f1[q] = 0.f; }
#pragma unroll
    for (int kt = 0; kt < 4; kt++) {
        float v00 = pst[psti(R + g     , kt*8 + tc)];
        float v01 = pst[psti(R + g + 8 , kt*8 + tc)];
        float v02 = pst[psti(R + g     , kt*8 + tc + 4)];
        float v03 = pst[psti(R + g + 8 , kt*8 + tc + 4)];
        float v10 = pst[psti(R + g + 16, kt*8 + tc)];
        float v11 = pst[psti(R + g + 24, kt*8 + tc)];
        float v12 = pst[psti(R + g + 16, kt*8 + tc + 4)];
        float v13 = pst[psti(R + g + 24, kt*8 + tc + 4)];
        uint32_t oh0[4] = {U(hif(v00)), U(hif(v01)), U(hif(v02)), U(hif(v03))};
        uint32_t ol0[4] = {U(lof(v00, hif(v00))), U(lof(v01, hif(v01))), U(lof(v02, hif(v02))), U(lof(v03, hif(v03)))};
        uint32_t oh1[4] = {U(hif(v10)), U(hif(v11)), U(hif(v12)), U(hif(v13))};
        uint32_t ol1[4] = {U(lof(v10, hif(v10))), U(lof(v11, hif(v11))), U(lof(v12, hif(v12))), U(lof(v13, hif(v13)))};
#pragma unroll
        for (int nt = 0; nt < 4; nt++) {
            uint32_t bh0 = U(Wvh[(nt*8 + g) * 36 + kt*8 + tc]);
            uint32_t bh1 = U(Wvh[(nt*8 + g) * 36 + kt*8 + tc + 4]);
            uint32_t bl0 = U(Wvl[(nt*8 + g) * 36 + kt*8 + tc]);
            uint32_t bl1 = U(Wvl[(nt*8 + g) * 36 + kt*8 + tc + 4]);
            mma8(&f0[nt*4], oh0, bh0, bh1);
            mma8(&f0[nt*4], oh0, bl0, bl1);
            mma8(&f0[nt*4], ol0, bh0, bh1);
            mma8(&f1[nt*4], oh1, bh0, bh1);
            mma8(&f1[nt*4], oh1, bl0, bl1);
            mma8(&f1[nt*4], ol1, bh0, bh1);
        }
    }

    l0 += __shfl_xor_sync(0xFFFFFFFFu, l0, 1); l0 += __shfl_xor_sync(0xFFFFFFFFu, l0, 2);
    l1 += __shfl_xor_sync(0xFFFFFFFFu, l1, 1); l1 += __shfl_xor_sync(0xFFFFFFFFu, l1, 2);
    l2 += __shfl_xor_sync(0xFFFFFFFFu, l2, 1); l2 += __shfl_xor_sync(0xFFFFFFFFu, l2, 2);
    l3 += __shfl_xor_sync(0xFFFFFFFFu, l3, 1); l3 += __shfl_xor_sync(0xFFFFFFFFu, l3, 2);
    float inv0 = 1.f / l0, inv1 = 1.f / l1, inv2 = 1.f / l2, inv3 = 1.f / l3;

#pragma unroll
    for (int nt = 0; nt < 4; nt++) {
        int c0 = nt * 8 + 2 * tc;
        float2 bb2 = *reinterpret_cast<const float2*>(&bvs[c0]);
        float2 v0 = make_float2(f0[nt*4+0] * inv0 + bb2.x, f0[nt*4+1] * inv0 + bb2.y);
        float2 v1 = make_float2(f0[nt*4+2] * inv1 + bb2.x, f0[nt*4+3] * inv1 + bb2.y);
        float2 v2 = make_float2(f1[nt*4+0] * inv2 + bb2.x, f1[nt*4+1] * inv2 + bb2.y);
        float2 v3 = make_float2(f1[nt*4+2] * inv3 + bb2.x, f1[nt*4+3] * inv3 + bb2.y);
        *reinterpret_cast<float2*>(out + (((size_t)i * NN + R + g     ) * HH + h) * DD + c0) = v0;
        *reinterpret_cast<float2*>(out + (((size_t)i * NN + R + g + 8 ) * HH + h) * DD + c0) = v1;
        *reinterpret_cast<float2*>(out + (((size_t)i * NN + R + g + 16) * HH + h) * DD + c0) = v2;
        *reinterpret_cast<float2*>(out + (((size_t)i * NN + R + g + 24) * HH + h) * DD + c0) = v3;
    }
}

// ---------------------------------------------------------------------------
extern "C" void kernel_launch(void* const* d_in, const int* in_sizes, int n_in,
                              void* d_out, int out_size) {
    const float* x    = (const float*)d_in[0];
    const float* mask = (const float*)d_in[1];
    const float* Wq   = (const float*)d_in[2];
    const float* bq   = (const float*)d_in[3];
    const float* Wk   = (const float*)d_in[4];
    const float* bk   = (const float*)d_in[5];
    const float* Wv   = (const float*)d_in[6];
    const float* bv   = (const float*)d_in[7];
    const float* Wb   = (const float*)d_in[8];
    const float* bb   = (const float*)d_in[9];
    float* out = (float*)d_out;

    cudaFuncSetAttribute(attn_kernel, cudaFuncAttributeMaxDynamicSharedMemorySize, DYN_BYTES);

    prep_trib_kernel<<<NN + HH, 256>>>(x, Wb, bb, Wq, bq, Wk, bk);
    attn_kernel<<<dim3(NN, HH), 256, DYN_BYTES>>>(x, mask, Wv, bv, out);
}

// round 9
// speedup vs baseline: 1.2871x; 1.0788x over previous
#include <cuda_runtime.h>
#include <cstdint>

#define NN 256
#define HH 4
#define DD 32
#define SCALE 0.1767766952966369f  /* 1/sqrt(32) */
#define L2E   1.4426950408889634f
#define M0L2E (14.0f * 1.4426950408889634f)

// ---------------- device globals ----------------
// trib2: fragment-coalesced layout
//   float index = (((h*32 + (j>>3))*128 + (k>>1))*8 + (j&7))*2 + (k&1)
__device__ __align__(16) float g_trib2[HH * NN * NN];
__device__ __align__(16) float g_M[HH * DD * DD];     // per-head scale*Wq^T Wk  [c][d]
__device__ __align__(16) float g_qb[HH * DD];
__device__ __align__(16) float g_u[HH * DD];
__device__ float g_c0[HH];

// ---------------- helpers ----------------
__device__ __forceinline__ float hif(float x) {
    return __uint_as_float(__float_as_uint(x) & 0xFFFFE000u);
}
__device__ __forceinline__ float lof(float x, float h) {
    return __uint_as_float(__float_as_uint(x - h) & 0xFFFFE000u);
}
__device__ __forceinline__ float rnaf(float x) {
    uint32_t r; asm("cvt.rna.tf32.f32 %0, %1;" : "=r"(r) : "f"(x));
    return __uint_as_float(r);
}
__device__ __forceinline__ float ex2(float x) {
    float r; asm("ex2.approx.ftz.f32 %0, %1;" : "=f"(r) : "f"(x)); return r;
}
__device__ __forceinline__ void mma8(float* d, const uint32_t* a, uint32_t b0, uint32_t b1) {
    asm volatile("mma.sync.aligned.m16n8k8.row.col.f32.tf32.tf32.f32 "
        "{%0,%1,%2,%3},{%4,%5,%6,%7},{%8,%9},{%0,%1,%2,%3};"
        : "+f"(d[0]), "+f"(d[1]), "+f"(d[2]), "+f"(d[3])
        : "r"(a[0]), "r"(a[1]), "r"(a[2]), "r"(a[3]), "r"(b0), "r"(b1));
}
#define U(x) __float_as_uint(x)

// ---------------------------------------------------------------------------
// prep + trib fused: blocks [0,256) = trib rows, blocks [256,260) = prep
// ---------------------------------------------------------------------------
__global__ void __launch_bounds__(256) prep_trib_kernel(
        const float* __restrict__ x,  const float* __restrict__ Wb,
        const float* __restrict__ bb, const float* __restrict__ Wq,
        const float* __restrict__ bq, const float* __restrict__ Wk,
        const float* __restrict__ bk) {
    int t = threadIdx.x;
    if (blockIdx.x < NN) {
        int jj = blockIdx.x, k = t;
        const float4* xr = reinterpret_cast<const float4*>(x + ((size_t)jj * NN + k) * DD);
        float4 xv[8];
#pragma unroll
        for (int q = 0; q < 8; q++) xv[q] = xr[q];
#pragma unroll
        for (int h = 0; h < HH; h++) {
            const float4* wr = reinterpret_cast<const float4*>(Wb + h * DD);
            float s = bb[h];
#pragma unroll
            for (int q = 0; q < 8; q++) {
                float4 ww = wr[q];
                s += xv[q].x * ww.x + xv[q].y * ww.y + xv[q].z * ww.z + xv[q].w * ww.w;
            }
            int idx = (((h * 32 + (jj >> 3)) * 128 + (k >> 1)) * 8 + (jj & 7)) * 2 + (k & 1);
            g_trib2[idx] = s * L2E;
        }
    } else {
        int h = blockIdx.x - NN;
        int d = t & 31, y = t >> 5;
#pragma unroll
        for (int cc = 0; cc < 4; cc++) {
            int c = y * 4 + cc;
            float s = 0.f;
#pragma unroll
            for (int r = 0; r < DD; r++)
                s += Wq[(h * DD + r) * DD + c] * Wk[(h * DD + r) * DD + d];
            g_M[(h * DD + c) * DD + d] = s * SCALE;
        }
        if (y == 0) {
            float s2 = 0.f, s3 = 0.f;
#pragma unroll
            for (int r = 0; r < DD; r++) {
                s2 += bq[h * DD + r] * Wk[(h * DD + r) * DD + d];
                s3 += Wq[(h * DD + r) * DD + d] * bk[h * DD + r];
            }
            g_qb[h * DD + d] = s2 * SCALE;
            g_u[h * DD + d]  = s3 * SCALE;
            if (d == 0) {
                float s4 = 0.f;
#pragma unroll
                for (int r = 0; r < DD; r++) s4 += bq[h * DD + r] * bk[h * DD + r];
                g_c0[h] = s4 * SCALE;
            }
        }
    }
}

// ---------------------------------------------------------------------------
// Fused attention: CTA=(i,h), 256 threads / 8 warps, warp = 32 query rows.
// Smem: XB  = rna(X) (d,d+4) packed float4 pairs, key-major, 40-word rows
//       PST = staging (Q~/P/O), 40-word rows, bit-2 XOR swizzle
// ---------------------------------------------------------------------------
#define XB_OFF  0
#define PST_OFF 40960          /* 256 * 40 * 4 */
#define DYN_BYTES 81920

// verified conflict-free: stores (16-lane phases) and scalar frag loads
__device__ __forceinline__ int psti(int row, int col) {
    return row * 40 + (col ^ (((row >> 2) & 1) << 2));
}

extern __shared__ char dynsm[];

__global__ void __launch_bounds__(256, 1) attn_kernel(
        const float* __restrict__ x, const float* __restrict__ mask,
        const float* __restrict__ Wv, const float* __restrict__ bv,
        float* __restrict__ out) {
    const int i = blockIdx.x, h = blockIdx.y;
    const int t = threadIdx.x;
    const int w = t >> 5, lane = t & 31, g = lane >> 2, tc = lane & 3;
    const int R = w * 32;

    float2* xb2 = reinterpret_cast<float2*>(dynsm + XB_OFF);
    float*  xbw = reinterpret_cast<float*>(dynsm + XB_OFF);
    float*  pst = reinterpret_cast<float*>(dynsm + PST_OFF);

    __shared__ __align__(16) float4 MB4s[DD * 20];        // M hi/lo pairs
    __shared__ __align__(8)  float Wvh[DD * 36], Wvl[DD * 36];
    __shared__ __align__(8)  float mbsm[NN];
    __shared__ float basej[NN];
    __shared__ __align__(8)  float qbs[DD], bvs[DD];

    // ================= prologue =================
    {
        const int j = t;
        float xv[DD], xr[DD];
        const float4* xg = reinterpret_cast<const float4*>(x + ((size_t)i * NN + j) * DD);
#pragma unroll
        for (int q = 0; q < 8; q++) {
            float4 v = xg[q];
            xv[4*q] = v.x; xv[4*q+1] = v.y; xv[4*q+2] = v.z; xv[4*q+3] = v.w;
        }
#pragma unroll
        for (int d = 0; d < DD; d++) xr[d] = rnaf(xv[d]);

        // XB: (d, d+4) pairs, key-major; float4 = {x[d0], x[d0+4], x[d0+1], x[d0+5]}
        {
            float4* xb4 = reinterpret_cast<float4*>(dynsm + XB_OFF);
#pragma unroll
            for (int kt = 0; kt < 4; kt++)
#pragma unroll
                for (int c = 0; c < 2; c++) {
                    int d0 = kt * 8 + 2 * c;
                    xb4[j * 10 + kt * 2 + c] =
                        make_float4(xr[d0], xr[d0 + 4], xr[d0 + 1], xr[d0 + 5]);
                }
        }
        // MB4s: M hi/lo pairs [d][kt][tc]
#pragma unroll
        for (int q = 0; q < 2; q++) {
            int e = t + q * 256;
            int d = e >> 4, r = e & 15, kt = r >> 2, cc = r & 3;
            int k0 = kt * 8 + cc;
            float m0 = g_M[((size_t)h * DD + k0) * DD + d];
            float m1 = g_M[((size_t)h * DD + k0 + 4) * DD + d];
            float h0 = hif(m0), h1 = hif(m1);
            MB4s[d * 20 + kt * 4 + cc] = make_float4(h0, lof(m0, h0), h1, lof(m1, h1));
        }
        // Wv hi/lo
#pragma unroll
        for (int q = 0; q < 4; q++) {
            int e = t + q * 256;
            int r = e >> 5, c = e & 31;
            float wv = Wv[((size_t)h * DD + r) * DD + c];
            float hh = hif(wv);
            Wvh[r * 36 + c] = hh;
            Wvl[r * 36 + c] = lof(wv, hh);
        }
        if (t < DD) qbs[t] = g_qb[h * DD + t];
        else if (t < 2 * DD) bvs[t - DD] = bv[h * DD + (t - DD)];
        mbsm[j] = (mask[i * NN + j] - 1.0f) * 1e9f * L2E;
        float cbv = g_c0[h];
#pragma unroll
        for (int c = 0; c < DD; c++) cbv += xv[c] * g_u[h * DD + c];
        basej[j] = cbv * L2E - M0L2E;
    }
    __syncthreads();

    // ================= Q~ = X M + qb (A = rna(X), B = Mh/Ml 2-pass) =========
    {
        float qt0[16], qt1[16];
#pragma unroll
        for (int q = 0; q < 16; q++) { qt0[q] = 0.f; qt1[q] = 0.f; }
#pragma unroll
        for (int kt = 0; kt < 4; kt++) {
            float2 pA0 = xb2[(R + g     ) * 20 + kt * 4 + tc];
            float2 pA1 = xb2[(R + g + 8 ) * 20 + kt * 4 + tc];
            float2 pB0 = xb2[(R + g + 16) * 20 + kt * 4 + tc];
            float2 pB1 = xb2[(R + g + 24) * 20 + kt * 4 + tc];
            uint32_t a0[4] = {U(pA0.x), U(pA1.x), U(pA0.y), U(pA1.y)};
            uint32_t a1[4] = {U(pB0.x), U(pB1.x), U(pB0.y), U(pB1.y)};
#pragma unroll
            for (int nt = 0; nt < 4; nt++) {
                float4 bm = MB4s[(nt * 8 + g) * 20 + kt * 4 + tc];
                mma8(&qt0[nt*4], a0, U(bm.x), U(bm.z));
                mma8(&qt0[nt*4], a0, U(bm.y), U(bm.w));
                mma8(&qt1[nt*4], a1, U(bm.x), U(bm.z));
                mma8(&qt1[nt*4], a1, U(bm.y), U(bm.w));
            }
        }
#pragma unroll
        for (int nt = 0; nt < 4; nt++) {
            int c0 = nt * 8 + 2 * tc;
            float2 qb2 = *reinterpret_cast<const float2*>(&qbs[c0]);
            *reinterpret_cast<float2*>(&pst[psti(R + g     , c0)]) =
                make_float2(rnaf(qt0[nt*4+0] + qb2.x), rnaf(qt0[nt*4+1] + qb2.y));
            *reinterpret_cast<float2*>(&pst[psti(R + g + 8 , c0)]) =
                make_float2(rnaf(qt0[nt*4+2] + qb2.x), rnaf(qt0[nt*4+3] + qb2.y));
            *reinterpret_cast<float2*>(&pst[psti(R + g + 16, c0)]) =
                make_float2(rnaf(qt1[nt*4+0] + qb2.x), rnaf(qt1[nt*4+1] + qb2.y));
            *reinterpret_cast<float2*>(&pst[psti(R + g + 24, c0)]) =
                make_float2(rnaf(qt1[nt*4+2] + qb2.x), rnaf(qt1[nt*4+3] + qb2.y));
        }
    }
    __syncwarp();

    // Persistent Q fragments
    uint32_t q0[16], q1[16];
#pragma unroll
    for (int kt = 0; kt < 4; kt++) {
        q0[kt*4+0] = U(pst[psti(R + g     , kt*8 + tc)]);
        q0[kt*4+1] = U(pst[psti(R + g + 8 , kt*8 + tc)]);
        q0[kt*4+2] = U(pst[psti(R + g     , kt*8 + tc + 4)]);
        q0[kt*4+3] = U(pst[psti(R + g + 8 , kt*8 + tc + 4)]);
        q1[kt*4+0] = U(pst[psti(R + g + 16, kt*8 + tc)]);
        q1[kt*4+1] = U(pst[psti(R + g + 24, kt*8 + tc)]);
        q1[kt*4+2] = U(pst[psti(R + g + 16, kt*8 + tc + 4)]);
        q1[kt*4+3] = U(pst[psti(R + g + 24, kt*8 + tc + 4)]);
    }
    const float base0 = basej[R + g], base1 = basej[R + g + 8];
    const float base2 = basej[R + g + 16], base3 = basej[R + g + 24];

    float o0[16], o1[16];
#pragma unroll
    for (int q = 0; q < 16; q++) { o0[q] = 0.f; o1[q] = 0.f; }
    float l0 = 0.f, l1 = 0.f, l2 = 0.f, l3 = 0.f;

    // trib2: per (m,nt) one coalesced 256B float2 load
    const float2* tpb = reinterpret_cast<const float2*>(g_trib2);
    const int jg = h * 32 + (R >> 3);
    // MMA2 B word-permutation within an 8-word group
    const int wb = ((g >> 1) & 1) * 4 + (g & 1) * 2 + (g >> 2);
    __syncwarp();

    // ================= main loop: 8 key-blocks of 32 =================
#pragma unroll 1
    for (int kb = 0; kb < NN; kb += 32) {
        // trib prefetch: coalesced
        float2 tb[16];
#pragma unroll
        for (int m = 0; m < 4; m++)
#pragma unroll
            for (int nt = 0; nt < 4; nt++)
                tb[m*4+nt] = tpb[((jg + m) << 10) + (kb * 4 + (nt * 4 + tc) * 8 + g)];

        // ---- MMA1: S = Q~ X^T (single tf32 pass) ----
        float s0[16], s1[16];
#pragma unroll
        for (int q = 0; q < 16; q++) { s0[q] = 0.f; s1[q] = 0.f; }
#pragma unroll
        for (int kt = 0; kt < 4; kt++) {
#pragma unroll
            for (int nt = 0; nt < 4; nt++) {
                float2 xb = xb2[(kb + nt*8 + g) * 20 + kt * 4 + tc];
                mma8(&s0[nt*4], &q0[kt*4], U(xb.x), U(xb.y));
                mma8(&s1[nt*4], &q1[kt*4], U(xb.x), U(xb.y));
            }
        }

        // ---- softmax; P (rna tf32) -> stage ----
#pragma unroll
        for (int nt = 0; nt < 4; nt++) {
            float2 mv = *reinterpret_cast<const float2*>(&mbsm[kb + nt*8 + 2*tc]);
            float t00 = rnaf(ex2(fmaf(s0[nt*4+0], L2E, base0 + mv.x + tb[nt].x)));
            float t01 = rnaf(ex2(fmaf(s0[nt*4+1], L2E, base0 + mv.y + tb[nt].y)));
            float t02 = rnaf(ex2(fmaf(s0[nt*4+2], L2E, base1 + mv.x + tb[4+nt].x)));
            float t03 = rnaf(ex2(fmaf(s0[nt*4+3], L2E, base1 + mv.y + tb[4+nt].y)));
            float t10 = rnaf(ex2(fmaf(s1[nt*4+0], L2E, base2 + mv.x + tb[8+nt].x)));
            float t11 = rnaf(ex2(fmaf(s1[nt*4+1], L2E, base2 + mv.y + tb[8+nt].y)));
            float t12 = rnaf(ex2(fmaf(s1[nt*4+2], L2E, base3 + mv.x + tb[12+nt].x)));
            float t13 = rnaf(ex2(fmaf(s1[nt*4+3], L2E, base3 + mv.y + tb[12+nt].y)));
            l0 += t00 + t01; l1 += t02 + t03; l2 += t10 + t11; l3 += t12 + t13;
            int c0 = nt * 8 + 2 * tc;
            *reinterpret_cast<float2*>(&pst[psti(R + g     , c0)]) = make_float2(t00, t01);
            *reinterpret_cast<float2*>(&pst[psti(R + g + 8 , c0)]) = make_float2(t02, t03);
            *reinterpret_cast<float2*>(&pst[psti(R + g + 16, c0)]) = make_float2(t10, t11);
            *reinterpret_cast<float2*>(&pst[psti(R + g + 24, c0)]) = make_float2(t12, t13);
        }
        __syncwarp();

        // ---- MMA2: O += P X (B direct from XB via word permutation) ----
#pragma unroll
        for (int kt = 0; kt < 4; kt++) {
            uint32_t a0[4], a1[4];
            a0[0] = U(pst[psti(R + g     , kt*8 + tc)]);
            a0[1] = U(pst[psti(R + g + 8 , kt*8 + tc)]);
            a0[2] = U(pst[psti(R + g     , kt*8 + tc + 4)]);
            a0[3] = U(pst[psti(R + g + 8 , kt*8 + tc + 4)]);
            a1[0] = U(pst[psti(R + g + 16, kt*8 + tc)]);
            a1[1] = U(pst[psti(R + g + 24, kt*8 + tc)]);
            a1[2] = U(pst[psti(R + g + 16, kt*8 + tc + 4)]);
            a1[3] = U(pst[psti(R + g + 24, kt*8 + tc + 4)]);
            int rw0 = (kb + kt * 8 + tc) * 40 + wb;
#pragma unroll
            for (int nt = 0; nt < 4; nt++) {
                uint32_t b0 = U(xbw[rw0 + nt * 8]);
                uint32_t b1 = U(xbw[rw0 + 160 + nt * 8]);
                mma8(&o0[nt*4], a0, b0, b1);
                mma8(&o1[nt*4], a1, b0, b1);
            }
        }
        __syncwarp();
    }

    // ================= epilogue: F = (O Wv^T)/l + bv (3xTF32) =================
#pragma unroll
    for (int nt = 0; nt < 4; nt++) {
        int c0 = nt * 8 + 2 * tc;
        *reinterpret_cast<float2*>(&pst[psti(R + g     , c0)]) = make_float2(o0[nt*4+0], o0[nt*4+1]);
        *reinterpret_cast<float2*>(&pst[psti(R + g + 8 , c0)]) = make_float2(o0[nt*4+2], o0[nt*4+3]);
        *reinterpret_cast<float2*>(&pst[psti(R + g + 16, c0)]) = make_float2(o1[nt*4+0], o1[nt*4+1]);
        *reinterpret_cast<float2*>(&pst[psti(R + g + 24, c0)]) = make_float2(o1[nt*4+2], o1[nt*4+3]);
    }
    __syncwarp();

    float f0[16], f1[16];
#pragma unroll
    for (int q = 0; q < 16; q++) { f0[q] = 0.f; f1[q] = 0.f; }
#pragma unroll
    for (int kt = 0; kt < 4; kt++) {
        float v00 = pst[psti(R + g     , kt*8 + tc)];
        float v01 = pst[psti(R + g + 8 , kt*8 + tc)];
        float v02 = pst[psti(R + g     , kt*8 + tc + 4)];
        float v03 = pst[psti(R + g + 8 , kt*8 + tc + 4)];
        float v10 = pst[psti(R + g + 16, kt*8 + tc)];
        float v11 = pst[psti(R + g + 24, kt*8 + tc)];
        float v12 = pst[psti(R + g + 16, kt*8 + tc + 4)];
        float v13 = pst[psti(R + g + 24, kt*8 + tc + 4)];
        uint32_t oh0[4] = {U(hif(v00)), U(hif(v01)), U(hif(v02)), U(hif(v03))};
        uint32_t ol0[4] = {U(lof(v00, hif(v00))), U(lof(v01, hif(v01))), U(lof(v02, hif(v02))), U(lof(v03, hif(v03)))};
        uint32_t oh1[4] = {U(hif(v10)), U(hif(v11)), U(hif(v12)), U(hif(v13))};
        uint32_t ol1[4] = {U(lof(v10, hif(v10))), U(lof(v11, hif(v11))), U(lof(v12, hif(v12))), U(lof(v13, hif(v13)))};
#pragma unroll
        for (int nt = 0; nt < 4; nt++) {
            uint32_t bh0 = U(Wvh[(nt*8 + g) * 36 + kt*8 + tc]);
            uint32_t bh1 = U(Wvh[(nt*8 + g) * 36 + kt*8 + tc + 4]);
            uint32_t bl0 = U(Wvl[(nt*8 + g) * 36 + kt*8 + tc]);
            uint32_t bl1 = U(Wvl[(nt*8 + g) * 36 + kt*8 + tc + 4]);
            mma8(&f0[nt*4], oh0, bh0, bh1);
            mma8(&f0[nt*4], oh0, bl0, bl1);
            mma8(&f0[nt*4], ol0, bh0, bh1);
            mma8(&f1[nt*4], oh1, bh0, bh1);
            mma8(&f1[nt*4], oh1, bl0, bl1);
            mma8(&f1[nt*4], ol1, bh0, bh1);
        }
    }

    l0 += __shfl_xor_sync(0xFFFFFFFFu, l0, 1); l0 += __shfl_xor_sync(0xFFFFFFFFu, l0, 2);
    l1 += __shfl_xor_sync(0xFFFFFFFFu, l1, 1); l1 += __shfl_xor_sync(0xFFFFFFFFu, l1, 2);
    l2 += __shfl_xor_sync(0xFFFFFFFFu, l2, 1); l2 += __shfl_xor_sync(0xFFFFFFFFu, l2, 2);
    l3 += __shfl_xor_sync(0xFFFFFFFFu, l3, 1); l3 += __shfl_xor_sync(0xFFFFFFFFu, l3, 2);
    float inv0 = 1.f / l0, inv1 = 1.f / l1, inv2 = 1.f / l2, inv3 = 1.f / l3;

#pragma unroll
    for (int nt = 0; nt < 4; nt++) {
        int c0 = nt * 8 + 2 * tc;
        float2 bb2 = *reinterpret_cast<const float2*>(&bvs[c0]);
        float2 v0 = make_float2(f0[nt*4+0] * inv0 + bb2.x, f0[nt*4+1] * inv0 + bb2.y);
        float2 v1 = make_float2(f0[nt*4+2] * inv1 + bb2.x, f0[nt*4+3] * inv1 + bb2.y);
        float2 v2 = make_float2(f1[nt*4+0] * inv2 + bb2.x, f1[nt*4+1] * inv2 + bb2.y);
        float2 v3 = make_float2(f1[nt*4+2] * inv3 + bb2.x, f1[nt*4+3] * inv3 + bb2.y);
        *reinterpret_cast<float2*>(out + (((size_t)i * NN + R + g     ) * HH + h) * DD + c0) = v0;
        *reinterpret_cast<float2*>(out + (((size_t)i * NN + R + g + 8 ) * HH + h) * DD + c0) = v1;
        *reinterpret_cast<float2*>(out + (((size_t)i * NN + R + g + 16) * HH + h) * DD + c0) = v2;
        *reinterpret_cast<float2*>(out + (((size_t)i * NN + R + g + 24) * HH + h) * DD + c0) = v3;
    }
}

// ---------------------------------------------------------------------------
extern "C" void kernel_launch(void* const* d_in, const int* in_sizes, int n_in,
                              void* d_out, int out_size) {
    const float* x    = (const float*)d_in[0];
    const float* mask = (const float*)d_in[1];
    const float* Wq   = (const float*)d_in[2];
    const float* bq   = (const float*)d_in[3];
    const float* Wk   = (const float*)d_in[4];
    const float* bk   = (const float*)d_in[5];
    const float* Wv   = (const float*)d_in[6];
    const float* bv   = (const float*)d_in[7];
    const float* Wb   = (const float*)d_in[8];
    const float* bb   = (const float*)d_in[9];
    float* out = (float*)d_out;

    cudaFuncSetAttribute(attn_kernel, cudaFuncAttributeMaxDynamicSharedMemorySize, DYN_BYTES);

    prep_trib_kernel<<<NN + HH, 256>>>(x, Wb, bb, Wq, bq, Wk, bk);
    attn_kernel<<<dim3(NN, HH), 256, DYN_BYTES>>>(x, mask, Wv, bv, out);
}

// round 10
// speedup vs baseline: 1.3675x; 1.0625x over previous
#include <cuda_runtime.h>
#include <cstdint>

#define NN 256
#define HH 4
#define DD 32
#define SCALE 0.1767766952966369f  /* 1/sqrt(32) */
#define L2E   1.4426950408889634f
#define M0L2E (14.0f * 1.4426950408889634f)

// ---------------- device globals ----------------
// trib2 fragment-coalesced: float idx = (((h*32+(j>>3))*128+(k>>1))*8+(j&7))*2+(k&1)
__device__ __align__(16) float g_trib2[HH * NN * NN];
__device__ __align__(16) float g_M[HH * DD * DD];
__device__ __align__(16) float g_qb[HH * DD];
__device__ __align__(16) float g_u[HH * DD];
__device__ float g_c0[HH];

// ---------------- helpers ----------------
__device__ __forceinline__ float hif(float x) {
    return __uint_as_float(__float_as_uint(x) & 0xFFFFE000u);
}
__device__ __forceinline__ float lof(float x, float h) {
    return __uint_as_float(__float_as_uint(x - h) & 0xFFFFE000u);
}
__device__ __forceinline__ float rnaf(float x) {
    uint32_t r; asm("cvt.rna.tf32.f32 %0, %1;" : "=r"(r) : "f"(x));
    return __uint_as_float(r);
}
__device__ __forceinline__ float ex2(float x) {
    float r; asm("ex2.approx.ftz.f32 %0, %1;" : "=f"(r) : "f"(x)); return r;
}
__device__ __forceinline__ void mma8(float* d, const uint32_t* a, uint32_t b0, uint32_t b1) {
    asm volatile("mma.sync.aligned.m16n8k8.row.col.f32.tf32.tf32.f32 "
        "{%0,%1,%2,%3},{%4,%5,%6,%7},{%8,%9},{%0,%1,%2,%3};"
        : "+f"(d[0]), "+f"(d[1]), "+f"(d[2]), "+f"(d[3])
        : "r"(a[0]), "r"(a[1]), "r"(a[2]), "r"(a[3]), "r"(b0), "r"(b1));
}
#define U(x) __float_as_uint(x)

// ---------------------------------------------------------------------------
// prep + trib fused
// ---------------------------------------------------------------------------
__global__ void __launch_bounds__(256) prep_trib_kernel(
        const float* __restrict__ x,  const float* __restrict__ Wb,
        const float* __restrict__ bb, const float* __restrict__ Wq,
        const float* __restrict__ bq, const float* __restrict__ Wk,
        const float* __restrict__ bk) {
    int t = threadIdx.x;
    if (blockIdx.x < NN) {
        int jj = blockIdx.x, k = t;
        const float4* xr = reinterpret_cast<const float4*>(x + ((size_t)jj * NN + k) * DD);
        float4 xv[8];
#pragma unroll
        for (int q = 0; q < 8; q++) xv[q] = xr[q];
#pragma unroll
        for (int h = 0; h < HH; h++) {
            const float4* wr = reinterpret_cast<const float4*>(Wb + h * DD);
            float s = bb[h];
#pragma unroll
            for (int q = 0; q < 8; q++) {
                float4 ww = wr[q];
                s += xv[q].x * ww.x + xv[q].y * ww.y + xv[q].z * ww.z + xv[q].w * ww.w;
            }
            int idx = (((h * 32 + (jj >> 3)) * 128 + (k >> 1)) * 8 + (jj & 7)) * 2 + (k & 1);
            g_trib2[idx] = s * L2E;
        }
    } else {
        int h = blockIdx.x - NN;
        int d = t & 31, y = t >> 5;
#pragma unroll
        for (int cc = 0; cc < 4; cc++) {
            int c = y * 4 + cc;
            float s = 0.f;
#pragma unroll
            for (int r = 0; r < DD; r++)
                s += Wq[(h * DD + r) * DD + c] * Wk[(h * DD + r) * DD + d];
            g_M[(h * DD + c) * DD + d] = s * SCALE;
        }
        if (y == 0) {
            float s2 = 0.f, s3 = 0.f;
#pragma unroll
            for (int r = 0; r < DD; r++) {
                s2 += bq[h * DD + r] * Wk[(h * DD + r) * DD + d];
                s3 += Wq[(h * DD + r) * DD + d] * bk[h * DD + r];
            }
            g_qb[h * DD + d] = s2 * SCALE;
            g_u[h * DD + d]  = s3 * SCALE;
            if (d == 0) {
                float s4 = 0.f;
#pragma unroll
                for (int r = 0; r < DD; r++) s4 += bq[h * DD + r] * bk[h * DD + r];
                g_c0[h] = s4 * SCALE;
            }
        }
    }
}

// ---------------------------------------------------------------------------
// Fused attention: CTA=(i,h), 256 threads / 8 warps, warp = 32 query rows.
// Smem: XB  = rna(X) (d,d+4) pairs, key-major, 40-word rows
//       XT  = rna(X) transposed [d][key-pairs], 264-word rows
//       PST = staging (Q~/P/O), 40-word rows, bit-2 XOR swizzle
// Main loop software-pipelined: MMA1(b+1) issued between P-stores(b) and MMA2(b).
// ---------------------------------------------------------------------------
#define XB_OFF  0
#define XT_OFF  40960          /* 256*40*4 */
#define PST_OFF 74752          /* + 32*264*4 = 33792 */
#define DYN_BYTES 115712       /* + 256*40*4 */
#define XTSTR 264

__device__ __forceinline__ int psti(int row, int col) {
    return row * 40 + (col ^ (((row >> 2) & 1) << 2));
}

extern __shared__ char dynsm[];

__global__ void __launch_bounds__(256, 1) attn_kernel(
        const float* __restrict__ x, const float* __restrict__ mask,
        const float* __restrict__ Wv, const float* __restrict__ bv,
        float* __restrict__ out) {
    const int i = blockIdx.x, h = blockIdx.y;
    const int t = threadIdx.x;
    const int w = t >> 5, lane = t & 31, g = lane >> 2, tc = lane & 3;
    const int R = w * 32;

    float2* xb2 = reinterpret_cast<float2*>(dynsm + XB_OFF);
    float2* xt2 = reinterpret_cast<float2*>(dynsm + XT_OFF);
    float*  pst = reinterpret_cast<float*>(dynsm + PST_OFF);

    __shared__ __align__(16) float4 MB4s[DD * 20];
    __shared__ __align__(8)  float Wvh[DD * 36], Wvl[DD * 36];
    __shared__ __align__(8)  float mbsm[NN];
    __shared__ float basej[NN];
    __shared__ __align__(8)  float qbs[DD], bvs[DD];

    // ================= prologue =================
    {
        const int j = t;
        float xv[DD], xr[DD];
        const float4* xg = reinterpret_cast<const float4*>(x + ((size_t)i * NN + j) * DD);
#pragma unroll
        for (int q = 0; q < 8; q++) {
            float4 v = xg[q];
            xv[4*q] = v.x; xv[4*q+1] = v.y; xv[4*q+2] = v.z; xv[4*q+3] = v.w;
        }
#pragma unroll
        for (int d = 0; d < DD; d++) xr[d] = rnaf(xv[d]);

        // XB
        {
            float4* xb4 = reinterpret_cast<float4*>(dynsm + XB_OFF);
#pragma unroll
            for (int kt = 0; kt < 4; kt++)
#pragma unroll
                for (int c = 0; c < 2; c++) {
                    int d0 = kt * 8 + 2 * c;
                    xb4[j * 10 + kt * 2 + c] =
                        make_float4(xr[d0], xr[d0 + 4], xr[d0 + 1], xr[d0 + 5]);
                }
        }
        // XT: transposed [d][key]; float slot fi pairs (key, key+4)
        {
            float* xtf = reinterpret_cast<float*>(dynsm + XT_OFF);
            int fi = (((j >> 3) * 4 + (j & 3)) << 1) + ((j >> 2) & 1);
#pragma unroll
            for (int d = 0; d < DD; d++)
                xtf[d * XTSTR + fi] = xr[d];
        }
        // MB4s
#pragma unroll
        for (int q = 0; q < 2; q++) {
            int e = t + q * 256;
            int d = e >> 4, r = e & 15, kt = r >> 2, cc = r & 3;
            int k0 = kt * 8 + cc;
            float m0 = g_M[((size_t)h * DD + k0) * DD + d];
            float m1 = g_M[((size_t)h * DD + k0 + 4) * DD + d];
            float h0 = hif(m0), h1 = hif(m1);
            MB4s[d * 20 + kt * 4 + cc] = make_float4(h0, lof(m0, h0), h1, lof(m1, h1));
        }
        // Wv hi/lo
#pragma unroll
        for (int q = 0; q < 4; q++) {
            int e = t + q * 256;
            int r = e >> 5, c = e & 31;
            float wv = Wv[((size_t)h * DD + r) * DD + c];
            float hh = hif(wv);
            Wvh[r * 36 + c] = hh;
            Wvl[r * 36 + c] = lof(wv, hh);
        }
        if (t < DD) qbs[t] = g_qb[h * DD + t];
        else if (t < 2 * DD) bvs[t - DD] = bv[h * DD + (t - DD)];
        mbsm[j] = (mask[i * NN + j] - 1.0f) * 1e9f * L2E;
        float cbv = g_c0[h];
#pragma unroll
        for (int c = 0; c < DD; c++) cbv += xv[c] * g_u[h * DD + c];
        basej[j] = cbv * L2E - M0L2E;
    }
    __syncthreads();

    // ================= Q~ = X M + qb (B = Mh/Ml 2-pass) =========
    {
        float qt0[16], qt1[16];
#pragma unroll
        for (int q = 0; q < 16; q++) { qt0[q] = 0.f; qt1[q] = 0.f; }
#pragma unroll
        for (int kt = 0; kt < 4; kt++) {
            float2 pA0 = xb2[(R + g     ) * 20 + kt * 4 + tc];
            float2 pA1 = xb2[(R + g + 8 ) * 20 + kt * 4 + tc];
            float2 pB0 = xb2[(R + g + 16) * 20 + kt * 4 + tc];
            float2 pB1 = xb2[(R + g + 24) * 20 + kt * 4 + tc];
            uint32_t a0[4] = {U(pA0.x), U(pA1.x), U(pA0.y), U(pA1.y)};
            uint32_t a1[4] = {U(pB0.x), U(pB1.x), U(pB0.y), U(pB1.y)};
#pragma unroll
            for (int nt = 0; nt < 4; nt++) {
                float4 bm = MB4s[(nt * 8 + g) * 20 + kt * 4 + tc];
                mma8(&qt0[nt*4], a0, U(bm.x), U(bm.z));
                mma8(&qt0[nt*4], a0, U(bm.y), U(bm.w));
                mma8(&qt1[nt*4], a1, U(bm.x), U(bm.z));
                mma8(&qt1[nt*4], a1, U(bm.y), U(bm.w));
            }
        }
#pragma unroll
        for (int nt = 0; nt < 4; nt++) {
            int c0 = nt * 8 + 2 * tc;
            float2 qb2 = *reinterpret_cast<const float2*>(&qbs[c0]);
            *reinterpret_cast<float2*>(&pst[psti(R + g     , c0)]) =
                make_float2(rnaf(qt0[nt*4+0] + qb2.x), rnaf(qt0[nt*4+1] + qb2.y));
            *reinterpret_cast<float2*>(&pst[psti(R + g + 8 , c0)]) =
                make_float2(rnaf(qt0[nt*4+2] + qb2.x), rnaf(qt0[nt*4+3] + qb2.y));
            *reinterpret_cast<float2*>(&pst[psti(R + g + 16, c0)]) =
                make_float2(rnaf(qt1[nt*4+0] + qb2.x), rnaf(qt1[nt*4+1] + qb2.y));
            *reinterpret_cast<float2*>(&pst[psti(R + g + 24, c0)]) =
                make_float2(rnaf(qt1[nt*4+2] + qb2.x), rnaf(qt1[nt*4+3] + qb2.y));
        }
    }
    __syncwarp();

    // Persistent Q fragments
    uint32_t q0[16], q1[16];
#pragma unroll
    for (int kt = 0; kt < 4; kt++) {
        q0[kt*4+0] = U(pst[psti(R + g     , kt*8 + tc)]);
        q0[kt*4+1] = U(pst[psti(R + g + 8 , kt*8 + tc)]);
        q0[kt*4+2] = U(pst[psti(R + g     , kt*8 + tc + 4)]);
        q0[kt*4+3] = U(pst[psti(R + g + 8 , kt*8 + tc + 4)]);
        q1[kt*4+0] = U(pst[psti(R + g + 16, kt*8 + tc)]);
        q1[kt*4+1] = U(pst[psti(R + g + 24, kt*8 + tc)]);
        q1[kt*4+2] = U(pst[psti(R + g + 16, kt*8 + tc + 4)]);
        q1[kt*4+3] = U(pst[psti(R + g + 24, kt*8 + tc + 4)]);
    }
    const float base0 = basej[R + g], base1 = basej[R + g + 8];
    const float base2 = basej[R + g + 16], base3 = basej[R + g + 24];

    float o0[16], o1[16];
#pragma unroll
    for (int q = 0; q < 16; q++) { o0[q] = 0.f; o1[q] = 0.f; }
    float l0 = 0.f, l1 = 0.f, l2 = 0.f, l3 = 0.f;

    const float2* tpb = reinterpret_cast<const float2*>(g_trib2);
    const int jg = h * 32 + (R >> 3);
    __syncwarp();

    // ---- pipelined main loop over 8 key-blocks of 32 ----
    float2 tbc[16], tbn[16];
    float sa[16], sb[16], na[16], nb[16];

    // prologue of pipeline: trib(0) + MMA1(0)
#pragma unroll
    for (int m = 0; m < 4; m++)
#pragma unroll
        for (int nt = 0; nt < 4; nt++)
            tbc[m*4+nt] = tpb[((jg + m) << 10) + ((nt * 4 + tc) * 8 + g)];
#pragma unroll
    for (int q = 0; q < 16; q++) { sa[q] = 0.f; sb[q] = 0.f; }
#pragma unroll
    for (int kt = 0; kt < 4; kt++)
#pragma unroll
        for (int nt = 0; nt < 4; nt++) {
            float2 xb = xb2[(nt*8 + g) * 20 + kt * 4 + tc];
            mma8(&sa[nt*4], &q0[kt*4], U(xb.x), U(xb.y));
            mma8(&sb[nt*4], &q1[kt*4], U(xb.x), U(xb.y));
        }

#pragma unroll
    for (int b = 0; b < 8; b++) {
        const int kb = b * 32;

        // ---- softmax(b); P (rna tf32) -> stage ----
#pragma unroll
        for (int nt = 0; nt < 4; nt++) {
            float2 mv = *reinterpret_cast<const float2*>(&mbsm[kb + nt*8 + 2*tc]);
            float t00 = rnaf(ex2(fmaf(sa[nt*4+0], L2E, base0 + mv.x + tbc[nt].x)));
            float t01 = rnaf(ex2(fmaf(sa[nt*4+1], L2E, base0 + mv.y + tbc[nt].y)));
            float t02 = rnaf(ex2(fmaf(sa[nt*4+2], L2E, base1 + mv.x + tbc[4+nt].x)));
            float t03 = rnaf(ex2(fmaf(sa[nt*4+3], L2E, base1 + mv.y + tbc[4+nt].y)));
            float t10 = rnaf(ex2(fmaf(sb[nt*4+0], L2E, base2 + mv.x + tbc[8+nt].x)));
            float t11 = rnaf(ex2(fmaf(sb[nt*4+1], L2E, base2 + mv.y + tbc[8+nt].y)));
            float t12 = rnaf(ex2(fmaf(sb[nt*4+2], L2E, base3 + mv.x + tbc[12+nt].x)));
            float t13 = rnaf(ex2(fmaf(sb[nt*4+3], L2E, base3 + mv.y + tbc[12+nt].y)));
            l0 += t00 + t01; l1 += t02 + t03; l2 += t10 + t11; l3 += t12 + t13;
            int c0 = nt * 8 + 2 * tc;
            *reinterpret_cast<float2*>(&pst[psti(R + g     , c0)]) = make_float2(t00, t01);
            *reinterpret_cast<float2*>(&pst[psti(R + g + 8 , c0)]) = make_float2(t02, t03);
            *reinterpret_cast<float2*>(&pst[psti(R + g + 16, c0)]) = make_float2(t10, t11);
            *reinterpret_cast<float2*>(&pst[psti(R + g + 24, c0)]) = make_float2(t12, t13);
        }
        __syncwarp();

        // ---- pipeline: trib(b+1) + MMA1(b+1) (independent of pst) ----
        if (b < 7) {
            const int kn = kb + 32;
#pragma unroll
            for (int m = 0; m < 4; m++)
#pragma unroll
                for (int nt = 0; nt < 4; nt++)
                    tbn[m*4+nt] = tpb[((jg + m) << 10) + (kn * 4 + (nt * 4 + tc) * 8 + g)];
#pragma unroll
            for (int q = 0; q < 16; q++) { na[q] = 0.f; nb[q] = 0.f; }
#pragma unroll
            for (int kt = 0; kt < 4; kt++)
#pragma unroll
                for (int nt = 0; nt < 4; nt++) {
                    float2 xb = xb2[(kn + nt*8 + g) * 20 + kt * 4 + tc];
                    mma8(&na[nt*4], &q0[kt*4], U(xb.x), U(xb.y));
                    mma8(&nb[nt*4], &q1[kt*4], U(xb.x), U(xb.y));
                }
        }

        // ---- MMA2(b): O += P X (A from pst, B float2 from XT) ----
#pragma unroll
        for (int kt = 0; kt < 4; kt++) {
            uint32_t a0[4], a1[4];
            a0[0] = U(pst[psti(R + g     , kt*8 + tc)]);
            a0[1] = U(pst[psti(R + g + 8 , kt*8 + tc)]);
            a0[2] = U(pst[psti(R + g     , kt*8 + tc + 4)]);
            a0[3] = U(pst[psti(R + g + 8 , kt*8 + tc + 4)]);
            a1[0] = U(pst[psti(R + g + 16, kt*8 + tc)]);
            a1[1] = U(pst[psti(R + g + 24, kt*8 + tc)]);
            a1[2] = U(pst[psti(R + g + 16, kt*8 + tc + 4)]);
            a1[3] = U(pst[psti(R + g + 24, kt*8 + tc + 4)]);
#pragma unroll
            for (int nt = 0; nt < 4; nt++) {
                float2 xt = xt2[(nt*8 + g) * (XTSTR / 2) + ((kb >> 3) + kt) * 4 + tc];
                mma8(&o0[nt*4], a0, U(xt.x), U(xt.y));
                mma8(&o1[nt*4], a1, U(xt.x), U(xt.y));
            }
        }
        __syncwarp();

        if (b < 7) {
#pragma unroll
            for (int q = 0; q < 16; q++) { sa[q] = na[q]; sb[q] = nb[q]; }
#pragma unroll
            for (int q = 0; q < 16; q++) tbc[q] = tbn[q];
        }
    }

    // ================= epilogue: F = (O Wv^T)/l + bv (3xTF32) =================
#pragma unroll
    for (int nt = 0; nt < 4; nt++) {
        int c0 = nt * 8 + 2 * tc;
        *reinterpret_cast<float2*>(&pst[psti(R + g     , c0)]) = make_float2(o0[nt*4+0], o0[nt*4+1]);
        *reinterpret_cast<float2*>(&pst[psti(R + g + 8 , c0)]) = make_float2(o0[nt*4+2], o0[nt*4+3]);
        *reinterpret_cast<float2*>(&pst[psti(R + g + 16, c0)]) = make_float2(o1[nt*4+0], o1[nt*4+1]);
        *reinterpret_cast<float2*>(&pst[psti(R + g + 24, c0)]) = make_float2(o1[nt*4+2], o1[nt*4+3]);
    }
    __syncwarp();

    float f0[16], f1[16];
#pragma unroll
    for (int q = 0; q < 16; q++) { f0[q] = 0.f; f1[q] = 0.f; }
#pragma unroll
    for (int kt = 0; kt < 4; kt++) {
        float v00 = pst[psti(R + g     , kt*8 + tc)];
        float v01 = pst[psti(R + g + 8 , kt*8 + tc)];
        float v02 = pst[psti(R + g     , kt*8 + tc + 4)];
        float v03 = pst[psti(R + g + 8 , kt*8 + tc + 4)];
        float v10 = pst[psti(R + g + 16, kt*8 + tc)];
        float v11 = pst[psti(R + g + 24, kt*8 + tc)];
        float v12 = pst[psti(R + g + 16, kt*8 + tc + 4)];
        float v13 = pst[psti(R + g + 24, kt*8 + tc + 4)];
        uint32_t oh0[4] = {U(hif(v00)), U(hif(v01)), U(hif(v02)), U(hif(v03))};
        uint32_t ol0[4] = {U(lof(v00, hif(v00))), U(lof(v01, hif(v01))), U(lof(v02, hif(v02))), U(lof(v03, hif(v03)))};
        uint32_t oh1[4] = {U(hif(v10)), U(hif(v11)), U(hif(v12)), U(hif(v13))};
        uint32_t ol1[4] = {U(lof(v10, hif(v10))), U(lof(v11, hif(v11))), U(lof(v12, hif(v12))), U(lof(v13, hif(v13)))};
#pragma unroll
        for (int nt = 0; nt < 4; nt++) {
            uint32_t bh0 = U(Wvh[(nt*8 + g) * 36 + kt*8 + tc]);
            uint32_t bh1 = U(Wvh[(nt*8 + g) * 36 + kt*8 + tc + 4]);
            uint32_t bl0 = U(Wvl[(nt*8 + g) * 36 + kt*8 + tc]);
            uint32_t bl1 = U(Wvl[(nt*8 + g) * 36 + kt*8 + tc + 4]);
            mma8(&f0[nt*4], oh0, bh0, bh1);
            mma8(&f0[nt*4], oh0, bl0, bl1);
            mma8(&f0[nt*4], ol0, bh0, bh1);
            mma8(&f1[nt*4], oh1, bh0, bh1);
            mma8(&f1[nt*4], oh1, bl0, bl1);
            mma8(&f1[nt*4], ol1, bh0, bh1);
        }
    }

    l0 += __shfl_xor_sync(0xFFFFFFFFu, l0, 1); l0 += __shfl_xor_sync(0xFFFFFFFFu, l0, 2);
    l1 += __shfl_xor_sync(0xFFFFFFFFu, l1, 1); l1 += __shfl_xor_sync(0xFFFFFFFFu, l1, 2);
    l2 += __shfl_xor_sync(0xFFFFFFFFu, l2, 1); l2 += __shfl_xor_sync(0xFFFFFFFFu, l2, 2);
    l3 += __shfl_xor_sync(0xFFFFFFFFu, l3, 1); l3 += __shfl_xor_sync(0xFFFFFFFFu, l3, 2);
    float inv0 = 1.f / l0, inv1 = 1.f / l1, inv2 = 1.f / l2, inv3 = 1.f / l3;

#pragma unroll
    for (int nt = 0; nt < 4; nt++) {
        int c0 = nt * 8 + 2 * tc;
        float2 bb2 = *reinterpret_cast<const float2*>(&bvs[c0]);
        float2 v0 = make_float2(f0[nt*4+0] * inv0 + bb2.x, f0[nt*4+1] * inv0 + bb2.y);
        float2 v1 = make_float2(f0[nt*4+2] * inv1 + bb2.x, f0[nt*4+3] * inv1 + bb2.y);
        float2 v2 = make_float2(f1[nt*4+0] * inv2 + bb2.x, f1[nt*4+1] * inv2 + bb2.y);
        float2 v3 = make_float2(f1[nt*4+2] * inv3 + bb2.x, f1[nt*4+3] * inv3 + bb2.y);
        *reinterpret_cast<float2*>(out + (((size_t)i * NN + R + g     ) * HH + h) * DD + c0) = v0;
        *reinterpret_cast<float2*>(out + (((size_t)i * NN + R + g + 8 ) * HH + h) * DD + c0) = v1;
        *reinterpret_cast<float2*>(out + (((size_t)i * NN + R + g + 16) * HH + h) * DD + c0) = v2;
        *reinterpret_cast<float2*>(out + (((size_t)i * NN + R + g + 24) * HH + h) * DD + c0) = v3;
    }
}

// ---------------------------------------------------------------------------
extern "C" void kernel_launch(void* const* d_in, const int* in_sizes, int n_in,
                              void* d_out, int out_size) {
    const float* x    = (const float*)d_in[0];
    const float* mask = (const float*)d_in[1];
    const float* Wq   = (const float*)d_in[2];
    const float* bq   = (const float*)d_in[3];
    const float* Wk   = (const float*)d_in[4];
    const float* bk   = (const float*)d_in[5];
    const float* Wv   = (const float*)d_in[6];
    const float* bv   = (const float*)d_in[7];
    const float* Wb   = (const float*)d_in[8];
    const float* bb   = (const float*)d_in[9];
    float* out = (float*)d_out;

    cudaFuncSetAttribute(attn_kernel, cudaFuncAttributeMaxDynamicSharedMemorySize, DYN_BYTES);

    prep_trib_kernel<<<NN + HH, 256>>>(x, Wb, bb, Wq, bq, Wk, bk);
    attn_kernel<<<dim3(NN, HH), 256, DYN_BYTES>>>(x, mask, Wv, bv, out);
}